// round 13
// baseline (speedup 1.0000x reference)
#include <cuda_runtime.h>
#include <cuda_fp16.h>
#include <cstdint>

#define IN_CH   256
#define OUT_CH  256
#define HID     128
#define S_MAX   16384
#define N_MAX   1100000

// ---- shared tile geometry (fp16 elems), BK=64 both kernels ----
#define TSA     72            // A tile stride (64 k + 8 pad)
#define SB      136           // B tile stride (128 n + 8 pad)
#define TA_OFF  0
#define TB_OFF  9216          // 128*72
#define TBUF    17920         // 9216 + 64*136
#define T_SMEM  71680         // 2 buffers * 17920 * 2B
#define TSST    133           // fp32 staging stride (transform epilogue)

// ---------------- scratch (device globals: no allocation allowed) ----------
__device__ float g_e[N_MAX];
__device__ float g_segsum[S_MAX];
__device__ int   g_idx64;
// X converted to fp16 by the gate kernel; consumed by the transform kernel.
// Rows >= n are never written and stay zero-initialized (safe to MMA).
__device__ __align__(16) __half g_Xh[(size_t)N_MAX * IN_CH];
// weights [k][n] row-major, single fp16 copy
__device__ __align__(16) __half g_W1h[IN_CH * HID];
__device__ __align__(16) __half g_Wth[IN_CH * OUT_CH];

// ---------------- helpers ---------------------------------------------------
__device__ __forceinline__ int load_idx(const void* idx, int i) {
    if (g_idx64) return (int)((const long long*)idx)[i];
    return ((const int*)idx)[i];
}

#define LDSM4(R, ADDR)                                                        \
    asm volatile("ldmatrix.sync.aligned.m8n8.x4.shared.b16 {%0,%1,%2,%3},[%4];" \
                 : "=r"(R[0]), "=r"(R[1]), "=r"(R[2]), "=r"(R[3]) : "r"(ADDR))
#define LDSM4T(R, ADDR)                                                       \
    asm volatile("ldmatrix.sync.aligned.m8n8.x4.trans.shared.b16 {%0,%1,%2,%3},[%4];" \
                 : "=r"(R[0]), "=r"(R[1]), "=r"(R[2]), "=r"(R[3]) : "r"(ADDR))
#define MMA_F16(C, A, B0, B1)                                                 \
    asm volatile("mma.sync.aligned.m16n8k16.row.col.f32.f16.f16.f32 "         \
                 "{%0,%1,%2,%3},{%4,%5,%6,%7},{%8,%9},{%0,%1,%2,%3};"         \
                 : "+f"(C[0]), "+f"(C[1]), "+f"(C[2]), "+f"(C[3])             \
                 : "r"(A[0]), "r"(A[1]), "r"(A[2]), "r"(A[3]),                \
                   "r"(B0), "r"(B1))
#define CP16(DST, SRC)                                                        \
    asm volatile("cp.async.ca.shared.global [%0],[%1],16;\n"                  \
                 :: "r"(DST), "l"(__cvta_generic_to_global(SRC)))
#define CP_COMMIT() asm volatile("cp.async.commit_group;")
#define CP_WAIT0()  asm volatile("cp.async.wait_group 0;")

// ---------------- tiny kernels ----------------------------------------------
__global__ void detect_idx_kernel(const void* __restrict__ idx, int n) {
    if (threadIdx.x == 0 && blockIdx.x == 0) {
        const long long* p = (const long long*)idx;
        int base = n / 4;
        int ok64 = 1;
        for (int i = 0; i < 8; i++) {
            long long v = p[base + i];
            if (v < 0 || v >= (1LL << 31)) ok64 = 0;
        }
        g_idx64 = ok64;
    }
}

__global__ void init_seg_kernel() {
    int s = blockIdx.x * blockDim.x + threadIdx.x;
    if (s < S_MAX) g_segsum[s] = 0.f;
}

__global__ void convert_w_kernel(const float* __restrict__ W1,
                                 const float* __restrict__ Wt) {
    int i = blockIdx.x * blockDim.x + threadIdx.x;
    if (i < IN_CH * OUT_CH) g_Wth[i] = __float2half_rn(Wt[i]);
    if (i < IN_CH * HID)    g_W1h[i] = __float2half_rn(W1[i]);
}

// ---------------- gate kernel (BK=64; shuffle-reduce epilogue) ---------------
// Unchanged from round 12 (proven: 330 us).
__global__ __launch_bounds__(256, 2) void gate_kernel(
    const float* __restrict__ X, const void* __restrict__ idx,
    const float* __restrict__ b1,
    const float* __restrict__ W2, const float* __restrict__ b2, int n)
{
    extern __shared__ __half sm[];
    __shared__ float red[256];
    __shared__ float sb1[128];
    __shared__ float sw2[128];

    const int tid  = threadIdx.x;
    const int lane = tid & 31;
    const int warp = tid >> 5;
    const int warpRow = (warp & 3) * 32;
    const int warpCol = (warp >> 2) * 64;
    const int rowBase = blockIdx.x * 128;

    const uint32_t smemBase = (uint32_t)__cvta_generic_to_shared(sm);

    if (tid < 128) { sb1[tid] = b1[tid]; sw2[tid] = W2[tid]; }

    float acc[2][8][4];
#pragma unroll
    for (int mt = 0; mt < 2; mt++)
#pragma unroll
        for (int nt = 0; nt < 8; nt++)
#pragma unroll
            for (int q = 0; q < 4; q++) acc[mt][nt][q] = 0.f;

    float4 aPref[8];

    auto loadA = [&](int kt) {
#pragma unroll
        for (int u = 0; u < 8; u++) {
            int f = tid + 256 * u;
            int row = f >> 4, kq = f & 15;
            int gr = rowBase + row;
            aPref[u] = (gr < n)
                ? *(const float4*)(X + (size_t)gr * IN_CH + kt * 64 + kq * 4)
                : make_float4(0.f, 0.f, 0.f, 0.f);
        }
    };
    auto stsA = [&](int b, int kt) {
#pragma unroll
        for (int u = 0; u < 8; u++) {
            int f = tid + 256 * u;
            int row = f >> 4, kq = f & 15;
            float4 v = aPref[u];
            __half2 h0 = __floats2half2_rn(v.x, v.y);
            __half2 h1 = __floats2half2_rn(v.z, v.w);
            uint2 hp = make_uint2(*(uint32_t*)&h0, *(uint32_t*)&h1);
            int off = b * TBUF + TA_OFF + row * TSA + kq * 4;
            *(uint2*)&sm[off] = hp;
            int gr = rowBase + row;
            if (gr < n)
                *(uint2*)&g_Xh[(size_t)gr * IN_CH + kt * 64 + kq * 4] = hp;
        }
    };
    auto cpB = [&](int b, int kt) {
#pragma unroll
        for (int u = 0; u < 4; u++) {
            int e = tid + 256 * u;
            int krow = e >> 4, c16 = e & 15;
            const __half* src = g_W1h + (size_t)(kt * 64 + krow) * HID + c16 * 8;
            uint32_t dst = smemBase +
                (uint32_t)(b * TBUF + TB_OFF + krow * SB + c16 * 8) * 2u;
            CP16(dst, src);
        }
    };
    auto compute = [&](int b) {
#pragma unroll
        for (int kk = 0; kk < 64; kk += 16) {
            uint32_t ah[2][4];
#pragma unroll
            for (int mt = 0; mt < 2; mt++) {
                int row = warpRow + mt * 16 + (lane & 15);
                int kof = kk + ((lane >> 4) << 3);
                LDSM4(ah[mt], smemBase +
                    (uint32_t)(b * TBUF + TA_OFF + row * TSA + kof) * 2u);
            }
#pragma unroll
            for (int p = 0; p < 4; p++) {
                int krow = kk + (lane & 7) + (((lane >> 3) & 1) << 3);
                int ncol = warpCol + p * 16 + ((lane >> 4) << 3);
                uint32_t bh[4];
                LDSM4T(bh, smemBase +
                    (uint32_t)(b * TBUF + TB_OFF + krow * SB + ncol) * 2u);
                MMA_F16(acc[0][2 * p],     ah[0], bh[0], bh[1]);
                MMA_F16(acc[1][2 * p],     ah[1], bh[0], bh[1]);
                MMA_F16(acc[0][2 * p + 1], ah[0], bh[2], bh[3]);
                MMA_F16(acc[1][2 * p + 1], ah[1], bh[2], bh[3]);
            }
        }
    };

    loadA(0);
    cpB(0, 0);
    CP_COMMIT();
    stsA(0, 0);
    CP_WAIT0();
    __syncthreads();

#pragma unroll 1
    for (int kt = 0; kt < 4; kt++) {
        int cur = kt & 1;
        bool more = (kt < 3);
        if (more) {
            loadA(kt + 1);
            cpB(1 - cur, kt + 1);
            CP_COMMIT();
        }
        compute(cur);
        if (more) {
            stsA(1 - cur, kt + 1);
            CP_WAIT0();
        }
        __syncthreads();
    }

#pragma unroll
    for (int mt = 0; mt < 2; mt++) {
        float p0 = 0.f, p1 = 0.f;
#pragma unroll
        for (int nt = 0; nt < 8; nt++) {
            int c0 = warpCol + nt * 8 + ((lane & 3) << 1);
            p0 += fmaxf(acc[mt][nt][0] + sb1[c0],     0.f) * sw2[c0];
            p0 += fmaxf(acc[mt][nt][1] + sb1[c0 + 1], 0.f) * sw2[c0 + 1];
            p1 += fmaxf(acc[mt][nt][2] + sb1[c0],     0.f) * sw2[c0];
            p1 += fmaxf(acc[mt][nt][3] + sb1[c0 + 1], 0.f) * sw2[c0 + 1];
        }
        p0 += __shfl_xor_sync(0xffffffffu, p0, 1);
        p0 += __shfl_xor_sync(0xffffffffu, p0, 2);
        p1 += __shfl_xor_sync(0xffffffffu, p1, 1);
        p1 += __shfl_xor_sync(0xffffffffu, p1, 2);
        if ((lane & 3) == 0) {
            int r = warpRow + mt * 16 + (lane >> 2);
            red[r * 2 + (warp >> 2)]       = p0;
            red[(r + 8) * 2 + (warp >> 2)] = p1;
        }
    }
    __syncthreads();

    if (tid < 128) {
        int gr = rowBase + tid;
        if (gr < n) {
            float g = b2[0] + red[tid * 2] + red[tid * 2 + 1];
            float e = expf(g);           // gate is O(1): no max-shift needed
            g_e[gr] = e;
            int s = load_idx(idx, gr);
            atomicAdd(&g_segsum[s], e);
        }
    }
}

// ---------------- transform kernel (BK=64; 3 CTAs/SM; L2 A-reuse grid) ------
// grid = (2, nTiles): blockIdx.x = column half (adjacent in launch order ->
// both halves of a row tile share the A tile via L2), blockIdx.y = row tile.
__global__ __launch_bounds__(256, 3) void transform_kernel(
    const void* __restrict__ idx, const float* __restrict__ bt,
    float* __restrict__ out, int n)
{
    extern __shared__ __half sm[];
    __shared__ int   sidx[128];
    __shared__ float srow[128];

    const int tid  = threadIdx.x;
    const int lane = tid & 31;
    const int warp = tid >> 5;
    const int warpRow = (warp & 3) * 32;
    const int warpCol = (warp >> 2) * 64;
    const int rowBase = blockIdx.y * 128;
    const int nBase   = blockIdx.x * 128;

    const uint32_t smemBase = (uint32_t)__cvta_generic_to_shared(sm);

    float acc[2][8][4];
#pragma unroll
    for (int mt = 0; mt < 2; mt++)
#pragma unroll
        for (int nt = 0; nt < 8; nt++)
#pragma unroll
            for (int q = 0; q < 4; q++) acc[mt][nt][q] = 0.f;

    if (tid < 128) {
        int gr = rowBase + tid;
        if (gr < n) {
            int s = load_idx(idx, gr);
            sidx[tid] = s;
            srow[tid] = g_e[gr] / fmaxf(g_segsum[s], 1e-16f);
        } else { sidx[tid] = -1; srow[tid] = 0.f; }
    }

    auto fill = [&](int b, int kt) {
#pragma unroll
        for (int u = 0; u < 4; u++) {
            int g = tid + 256 * u;
            int row = g >> 3, kq = g & 7;
            const __half* s =
                g_Xh + (size_t)(rowBase + row) * IN_CH + kt * 64 + kq * 8;
            uint32_t dst = smemBase +
                (uint32_t)(b * TBUF + TA_OFF + row * TSA + kq * 8) * 2u;
            CP16(dst, s);
        }
#pragma unroll
        for (int u = 0; u < 4; u++) {
            int e = tid + 256 * u;
            int krow = e >> 4, c16 = e & 15;
            const __half* s =
                g_Wth + (size_t)(kt * 64 + krow) * OUT_CH + nBase + c16 * 8;
            uint32_t dst = smemBase +
                (uint32_t)(b * TBUF + TB_OFF + krow * SB + c16 * 8) * 2u;
            CP16(dst, s);
        }
    };
    auto compute = [&](int b) {
#pragma unroll
        for (int kk = 0; kk < 64; kk += 16) {
            uint32_t ah[2][4];
#pragma unroll
            for (int mt = 0; mt < 2; mt++) {
                int row = warpRow + mt * 16 + (lane & 15);
                int kof = kk + ((lane >> 4) << 3);
                LDSM4(ah[mt], smemBase +
                    (uint32_t)(b * TBUF + TA_OFF + row * TSA + kof) * 2u);
            }
#pragma unroll
            for (int p = 0; p < 4; p++) {
                int krow = kk + (lane & 7) + (((lane >> 3) & 1) << 3);
                int ncol = warpCol + p * 16 + ((lane >> 4) << 3);
                uint32_t bh[4];
                LDSM4T(bh, smemBase +
                    (uint32_t)(b * TBUF + TB_OFF + krow * SB + ncol) * 2u);
                MMA_F16(acc[0][2 * p],     ah[0], bh[0], bh[1]);
                MMA_F16(acc[1][2 * p],     ah[1], bh[0], bh[1]);
                MMA_F16(acc[0][2 * p + 1], ah[0], bh[2], bh[3]);
                MMA_F16(acc[1][2 * p + 1], ah[1], bh[2], bh[3]);
            }
        }
    };

    fill(0, 0);
    CP_COMMIT();
    CP_WAIT0();
    __syncthreads();

#pragma unroll 1
    for (int kt = 0; kt < 4; kt++) {
        int cur = kt & 1;
        bool more = (kt < 3);
        if (more) {
            fill(1 - cur, kt + 1);
            CP_COMMIT();
        }
        compute(cur);
        if (more) CP_WAIT0();
        __syncthreads();
    }

    float* Tsm = (float*)sm;
#pragma unroll
    for (int mt = 0; mt < 2; mt++)
#pragma unroll
        for (int nt = 0; nt < 8; nt++) {
            int r0 = warpRow + mt * 16 + (lane >> 2);
            int c0 = warpCol + nt * 8 + ((lane & 3) << 1);
            Tsm[r0 * TSST + c0]           = acc[mt][nt][0];
            Tsm[r0 * TSST + c0 + 1]       = acc[mt][nt][1];
            Tsm[(r0 + 8) * TSST + c0]     = acc[mt][nt][2];
            Tsm[(r0 + 8) * TSST + c0 + 1] = acc[mt][nt][3];
        }
    __syncthreads();

    {
        int c = tid & 127;
        int rStart = (tid >> 7) * 64;
        float btc = bt[nBase + c];
        float a = 0.f;
        int prev = -1;
        for (int r = rStart; r < rStart + 64; r++) {
            int s = sidx[r];
            if (s < 0) break;
            if (s != prev) {
                if (prev >= 0)
                    atomicAdd(&out[(size_t)prev * OUT_CH + nBase + c], a);
                a = 0.f;
                prev = s;
            }
            a = fmaf(fmaxf(Tsm[r * TSST + c] + btc, 0.f), srow[r], a);
        }
        if (prev >= 0)
            atomicAdd(&out[(size_t)prev * OUT_CH + nBase + c], a);
    }
}

// ---------------- launch -----------------------------------------------------
extern "C" void kernel_launch(void* const* d_in, const int* in_sizes, int n_in,
                              void* d_out, int out_size)
{
    const float* X   = (const float*)d_in[0];
    const void*  idx = d_in[1];
    int base = (n_in >= 9 && in_sizes[2] <= 16) ? 3 : 2;
    const float* W1 = (const float*)d_in[base + 0];
    const float* b1 = (const float*)d_in[base + 1];
    const float* W2 = (const float*)d_in[base + 2];
    const float* b2 = (const float*)d_in[base + 3];
    const float* Wt = (const float*)d_in[base + 4];
    const float* bt = (const float*)d_in[base + 5];

    const int n = in_sizes[0] / IN_CH;
    float* out = (float*)d_out;

    cudaFuncSetAttribute(gate_kernel,
                         cudaFuncAttributeMaxDynamicSharedMemorySize, T_SMEM);
    cudaFuncSetAttribute(transform_kernel,
                         cudaFuncAttributeMaxDynamicSharedMemorySize, T_SMEM);

    cudaMemsetAsync(d_out, 0, (size_t)out_size * sizeof(float), 0);
    detect_idx_kernel<<<1, 32>>>(idx, n);
    init_seg_kernel<<<(S_MAX + 255) / 256, 256>>>();
    convert_w_kernel<<<(IN_CH * OUT_CH + 255) / 256, 256>>>(W1, Wt);

    const int nTiles = (n + 127) / 128;
    gate_kernel<<<dim3(nTiles, 1), 256, T_SMEM>>>(X, idx, b1, W2, b2, n);
    transform_kernel<<<dim3(2, nTiles), 256, T_SMEM>>>(idx, bt, out, n);
}

// round 14
// speedup vs baseline: 1.3989x; 1.3989x over previous
#include <cuda_runtime.h>
#include <cuda_fp16.h>
#include <cstdint>

#define IN_CH   256
#define OUT_CH  256
#define HID     128
#define S_MAX   16384
#define N_MAX   1100000

// ---- shared tile geometry (fp16 elems), BK=64 both kernels ----
#define TSA     72            // A tile stride (64 k + 8 pad)
#define SB      136           // B tile stride (128 n + 8 pad)
#define TA_OFF  0
#define TB_OFF  9216          // 128*72
#define TBUF    17920         // 9216 + 64*136
#define T_SMEM  71680         // 2 buffers * 17920 * 2B
#define TSST    133           // fp32 staging stride (transform epilogue)

// ---------------- scratch (device globals: no allocation allowed) ----------
__device__ float g_e[N_MAX];
__device__ float g_segsum[S_MAX];
__device__ int   g_idx64;
// X converted to fp16 by the gate kernel; consumed by the transform kernel.
// Rows >= n are never written and stay zero-initialized (safe to MMA).
__device__ __align__(16) __half g_Xh[(size_t)N_MAX * IN_CH];
// weights [k][n] row-major, single fp16 copy
__device__ __align__(16) __half g_W1h[IN_CH * HID];
__device__ __align__(16) __half g_Wth[IN_CH * OUT_CH];

// ---------------- helpers ---------------------------------------------------
__device__ __forceinline__ int load_idx(const void* idx, int i) {
    if (g_idx64) return (int)((const long long*)idx)[i];
    return ((const int*)idx)[i];
}

#define LDSM4(R, ADDR)                                                        \
    asm volatile("ldmatrix.sync.aligned.m8n8.x4.shared.b16 {%0,%1,%2,%3},[%4];" \
                 : "=r"(R[0]), "=r"(R[1]), "=r"(R[2]), "=r"(R[3]) : "r"(ADDR))
#define LDSM4T(R, ADDR)                                                       \
    asm volatile("ldmatrix.sync.aligned.m8n8.x4.trans.shared.b16 {%0,%1,%2,%3},[%4];" \
                 : "=r"(R[0]), "=r"(R[1]), "=r"(R[2]), "=r"(R[3]) : "r"(ADDR))
#define MMA_F16(C, A, B0, B1)                                                 \
    asm volatile("mma.sync.aligned.m16n8k16.row.col.f32.f16.f16.f32 "         \
                 "{%0,%1,%2,%3},{%4,%5,%6,%7},{%8,%9},{%0,%1,%2,%3};"         \
                 : "+f"(C[0]), "+f"(C[1]), "+f"(C[2]), "+f"(C[3])             \
                 : "r"(A[0]), "r"(A[1]), "r"(A[2]), "r"(A[3]),                \
                   "r"(B0), "r"(B1))
#define CP16(DST, SRC)                                                        \
    asm volatile("cp.async.ca.shared.global [%0],[%1],16;\n"                  \
                 :: "r"(DST), "l"(__cvta_generic_to_global(SRC)))
#define CP_COMMIT() asm volatile("cp.async.commit_group;")
#define CP_WAIT0()  asm volatile("cp.async.wait_group 0;")

// ---------------- tiny kernels ----------------------------------------------
__global__ void detect_idx_kernel(const void* __restrict__ idx, int n) {
    if (threadIdx.x == 0 && blockIdx.x == 0) {
        const long long* p = (const long long*)idx;
        int base = n / 4;
        int ok64 = 1;
        for (int i = 0; i < 8; i++) {
            long long v = p[base + i];
            if (v < 0 || v >= (1LL << 31)) ok64 = 0;
        }
        g_idx64 = ok64;
    }
}

__global__ void init_seg_kernel() {
    int s = blockIdx.x * blockDim.x + threadIdx.x;
    if (s < S_MAX) g_segsum[s] = 0.f;
}

__global__ void convert_w_kernel(const float* __restrict__ W1,
                                 const float* __restrict__ Wt) {
    int i = blockIdx.x * blockDim.x + threadIdx.x;
    if (i < IN_CH * OUT_CH) g_Wth[i] = __float2half_rn(Wt[i]);
    if (i < IN_CH * HID)    g_W1h[i] = __float2half_rn(W1[i]);
}

// ---------------- gate kernel (BK=64; shuffle-reduce epilogue) ---------------
// Unchanged from round 12 (proven: 330 us).
__global__ __launch_bounds__(256, 2) void gate_kernel(
    const float* __restrict__ X, const void* __restrict__ idx,
    const float* __restrict__ b1,
    const float* __restrict__ W2, const float* __restrict__ b2, int n)
{
    extern __shared__ __half sm[];
    __shared__ float red[256];
    __shared__ float sb1[128];
    __shared__ float sw2[128];

    const int tid  = threadIdx.x;
    const int lane = tid & 31;
    const int warp = tid >> 5;
    const int warpRow = (warp & 3) * 32;
    const int warpCol = (warp >> 2) * 64;
    const int rowBase = blockIdx.x * 128;

    const uint32_t smemBase = (uint32_t)__cvta_generic_to_shared(sm);

    if (tid < 128) { sb1[tid] = b1[tid]; sw2[tid] = W2[tid]; }

    float acc[2][8][4];
#pragma unroll
    for (int mt = 0; mt < 2; mt++)
#pragma unroll
        for (int nt = 0; nt < 8; nt++)
#pragma unroll
            for (int q = 0; q < 4; q++) acc[mt][nt][q] = 0.f;

    float4 aPref[8];

    auto loadA = [&](int kt) {
#pragma unroll
        for (int u = 0; u < 8; u++) {
            int f = tid + 256 * u;
            int row = f >> 4, kq = f & 15;
            int gr = rowBase + row;
            aPref[u] = (gr < n)
                ? *(const float4*)(X + (size_t)gr * IN_CH + kt * 64 + kq * 4)
                : make_float4(0.f, 0.f, 0.f, 0.f);
        }
    };
    auto stsA = [&](int b, int kt) {
#pragma unroll
        for (int u = 0; u < 8; u++) {
            int f = tid + 256 * u;
            int row = f >> 4, kq = f & 15;
            float4 v = aPref[u];
            __half2 h0 = __floats2half2_rn(v.x, v.y);
            __half2 h1 = __floats2half2_rn(v.z, v.w);
            uint2 hp = make_uint2(*(uint32_t*)&h0, *(uint32_t*)&h1);
            int off = b * TBUF + TA_OFF + row * TSA + kq * 4;
            *(uint2*)&sm[off] = hp;
            int gr = rowBase + row;
            if (gr < n)
                *(uint2*)&g_Xh[(size_t)gr * IN_CH + kt * 64 + kq * 4] = hp;
        }
    };
    auto cpB = [&](int b, int kt) {
#pragma unroll
        for (int u = 0; u < 4; u++) {
            int e = tid + 256 * u;
            int krow = e >> 4, c16 = e & 15;
            const __half* src = g_W1h + (size_t)(kt * 64 + krow) * HID + c16 * 8;
            uint32_t dst = smemBase +
                (uint32_t)(b * TBUF + TB_OFF + krow * SB + c16 * 8) * 2u;
            CP16(dst, src);
        }
    };
    auto compute = [&](int b) {
#pragma unroll
        for (int kk = 0; kk < 64; kk += 16) {
            uint32_t ah[2][4];
#pragma unroll
            for (int mt = 0; mt < 2; mt++) {
                int row = warpRow + mt * 16 + (lane & 15);
                int kof = kk + ((lane >> 4) << 3);
                LDSM4(ah[mt], smemBase +
                    (uint32_t)(b * TBUF + TA_OFF + row * TSA + kof) * 2u);
            }
#pragma unroll
            for (int p = 0; p < 4; p++) {
                int krow = kk + (lane & 7) + (((lane >> 3) & 1) << 3);
                int ncol = warpCol + p * 16 + ((lane >> 4) << 3);
                uint32_t bh[4];
                LDSM4T(bh, smemBase +
                    (uint32_t)(b * TBUF + TB_OFF + krow * SB + ncol) * 2u);
                MMA_F16(acc[0][2 * p],     ah[0], bh[0], bh[1]);
                MMA_F16(acc[1][2 * p],     ah[1], bh[0], bh[1]);
                MMA_F16(acc[0][2 * p + 1], ah[0], bh[2], bh[3]);
                MMA_F16(acc[1][2 * p + 1], ah[1], bh[2], bh[3]);
            }
        }
    };

    loadA(0);
    cpB(0, 0);
    CP_COMMIT();
    stsA(0, 0);
    CP_WAIT0();
    __syncthreads();

#pragma unroll 1
    for (int kt = 0; kt < 4; kt++) {
        int cur = kt & 1;
        bool more = (kt < 3);
        if (more) {
            loadA(kt + 1);
            cpB(1 - cur, kt + 1);
            CP_COMMIT();
        }
        compute(cur);
        if (more) {
            stsA(1 - cur, kt + 1);
            CP_WAIT0();
        }
        __syncthreads();
    }

#pragma unroll
    for (int mt = 0; mt < 2; mt++) {
        float p0 = 0.f, p1 = 0.f;
#pragma unroll
        for (int nt = 0; nt < 8; nt++) {
            int c0 = warpCol + nt * 8 + ((lane & 3) << 1);
            p0 += fmaxf(acc[mt][nt][0] + sb1[c0],     0.f) * sw2[c0];
            p0 += fmaxf(acc[mt][nt][1] + sb1[c0 + 1], 0.f) * sw2[c0 + 1];
            p1 += fmaxf(acc[mt][nt][2] + sb1[c0],     0.f) * sw2[c0];
            p1 += fmaxf(acc[mt][nt][3] + sb1[c0 + 1], 0.f) * sw2[c0 + 1];
        }
        p0 += __shfl_xor_sync(0xffffffffu, p0, 1);
        p0 += __shfl_xor_sync(0xffffffffu, p0, 2);
        p1 += __shfl_xor_sync(0xffffffffu, p1, 1);
        p1 += __shfl_xor_sync(0xffffffffu, p1, 2);
        if ((lane & 3) == 0) {
            int r = warpRow + mt * 16 + (lane >> 2);
            red[r * 2 + (warp >> 2)]       = p0;
            red[(r + 8) * 2 + (warp >> 2)] = p1;
        }
    }
    __syncthreads();

    if (tid < 128) {
        int gr = rowBase + tid;
        if (gr < n) {
            float g = b2[0] + red[tid * 2] + red[tid * 2 + 1];
            float e = expf(g);           // gate is O(1): no max-shift needed
            g_e[gr] = e;
            int s = load_idx(idx, gr);
            atomicAdd(&g_segsum[s], e);
        }
    }
}

// ---------------- transform kernel (BK=64; 2 CTAs/SM; L2 A-reuse grid) ------
// R12 body (proven 484 us) with ONLY the grid swapped: blockIdx.x = column
// half (adjacent in launch order -> A tile shared via L2), blockIdx.y = row.
__global__ __launch_bounds__(256, 2) void transform_kernel(
    const void* __restrict__ idx, const float* __restrict__ bt,
    float* __restrict__ out, int n)
{
    extern __shared__ __half sm[];
    __shared__ int   sidx[128];
    __shared__ float srow[128];

    const int tid  = threadIdx.x;
    const int lane = tid & 31;
    const int warp = tid >> 5;
    const int warpRow = (warp & 3) * 32;
    const int warpCol = (warp >> 2) * 64;
    const int rowBase = blockIdx.y * 128;
    const int nBase   = blockIdx.x * 128;

    const uint32_t smemBase = (uint32_t)__cvta_generic_to_shared(sm);

    float acc[2][8][4];
#pragma unroll
    for (int mt = 0; mt < 2; mt++)
#pragma unroll
        for (int nt = 0; nt < 8; nt++)
#pragma unroll
            for (int q = 0; q < 4; q++) acc[mt][nt][q] = 0.f;

    if (tid < 128) {
        int gr = rowBase + tid;
        if (gr < n) {
            int s = load_idx(idx, gr);
            sidx[tid] = s;
            srow[tid] = g_e[gr] / fmaxf(g_segsum[s], 1e-16f);
        } else { sidx[tid] = -1; srow[tid] = 0.f; }
    }

    auto fill = [&](int b, int kt) {
#pragma unroll
        for (int u = 0; u < 4; u++) {
            int g = tid + 256 * u;
            int row = g >> 3, kq = g & 7;
            const __half* s =
                g_Xh + (size_t)(rowBase + row) * IN_CH + kt * 64 + kq * 8;
            uint32_t dst = smemBase +
                (uint32_t)(b * TBUF + TA_OFF + row * TSA + kq * 8) * 2u;
            CP16(dst, s);
        }
#pragma unroll
        for (int u = 0; u < 4; u++) {
            int e = tid + 256 * u;
            int krow = e >> 4, c16 = e & 15;
            const __half* s =
                g_Wth + (size_t)(kt * 64 + krow) * OUT_CH + nBase + c16 * 8;
            uint32_t dst = smemBase +
                (uint32_t)(b * TBUF + TB_OFF + krow * SB + c16 * 8) * 2u;
            CP16(dst, s);
        }
    };
    auto compute = [&](int b) {
#pragma unroll
        for (int kk = 0; kk < 64; kk += 16) {
            uint32_t ah[2][4];
#pragma unroll
            for (int mt = 0; mt < 2; mt++) {
                int row = warpRow + mt * 16 + (lane & 15);
                int kof = kk + ((lane >> 4) << 3);
                LDSM4(ah[mt], smemBase +
                    (uint32_t)(b * TBUF + TA_OFF + row * TSA + kof) * 2u);
            }
#pragma unroll
            for (int p = 0; p < 4; p++) {
                int krow = kk + (lane & 7) + (((lane >> 3) & 1) << 3);
                int ncol = warpCol + p * 16 + ((lane >> 4) << 3);
                uint32_t bh[4];
                LDSM4T(bh, smemBase +
                    (uint32_t)(b * TBUF + TB_OFF + krow * SB + ncol) * 2u);
                MMA_F16(acc[0][2 * p],     ah[0], bh[0], bh[1]);
                MMA_F16(acc[1][2 * p],     ah[1], bh[0], bh[1]);
                MMA_F16(acc[0][2 * p + 1], ah[0], bh[2], bh[3]);
                MMA_F16(acc[1][2 * p + 1], ah[1], bh[2], bh[3]);
            }
        }
    };

    fill(0, 0);
    CP_COMMIT();
    CP_WAIT0();
    __syncthreads();

#pragma unroll 1
    for (int kt = 0; kt < 4; kt++) {
        int cur = kt & 1;
        bool more = (kt < 3);
        if (more) {
            fill(1 - cur, kt + 1);
            CP_COMMIT();
        }
        compute(cur);
        if (more) CP_WAIT0();
        __syncthreads();
    }

    float* Tsm = (float*)sm;
#pragma unroll
    for (int mt = 0; mt < 2; mt++)
#pragma unroll
        for (int nt = 0; nt < 8; nt++) {
            int r0 = warpRow + mt * 16 + (lane >> 2);
            int c0 = warpCol + nt * 8 + ((lane & 3) << 1);
            Tsm[r0 * TSST + c0]           = acc[mt][nt][0];
            Tsm[r0 * TSST + c0 + 1]       = acc[mt][nt][1];
            Tsm[(r0 + 8) * TSST + c0]     = acc[mt][nt][2];
            Tsm[(r0 + 8) * TSST + c0 + 1] = acc[mt][nt][3];
        }
    __syncthreads();

    {
        int c = tid & 127;
        int rStart = (tid >> 7) * 64;
        float btc = bt[nBase + c];
        float a = 0.f;
        int prev = -1;
        for (int r = rStart; r < rStart + 64; r++) {
            int s = sidx[r];
            if (s < 0) break;
            if (s != prev) {
                if (prev >= 0)
                    atomicAdd(&out[(size_t)prev * OUT_CH + nBase + c], a);
                a = 0.f;
                prev = s;
            }
            a = fmaf(fmaxf(Tsm[r * TSST + c] + btc, 0.f), srow[r], a);
        }
        if (prev >= 0)
            atomicAdd(&out[(size_t)prev * OUT_CH + nBase + c], a);
    }
}

// ---------------- launch -----------------------------------------------------
extern "C" void kernel_launch(void* const* d_in, const int* in_sizes, int n_in,
                              void* d_out, int out_size)
{
    const float* X   = (const float*)d_in[0];
    const void*  idx = d_in[1];
    int base = (n_in >= 9 && in_sizes[2] <= 16) ? 3 : 2;
    const float* W1 = (const float*)d_in[base + 0];
    const float* b1 = (const float*)d_in[base + 1];
    const float* W2 = (const float*)d_in[base + 2];
    const float* b2 = (const float*)d_in[base + 3];
    const float* Wt = (const float*)d_in[base + 4];
    const float* bt = (const float*)d_in[base + 5];

    const int n = in_sizes[0] / IN_CH;
    float* out = (float*)d_out;

    cudaFuncSetAttribute(gate_kernel,
                         cudaFuncAttributeMaxDynamicSharedMemorySize, T_SMEM);
    cudaFuncSetAttribute(transform_kernel,
                         cudaFuncAttributeMaxDynamicSharedMemorySize, T_SMEM);

    cudaMemsetAsync(d_out, 0, (size_t)out_size * sizeof(float), 0);
    detect_idx_kernel<<<1, 32>>>(idx, n);
    init_seg_kernel<<<(S_MAX + 255) / 256, 256>>>();
    convert_w_kernel<<<(IN_CH * OUT_CH + 255) / 256, 256>>>(W1, Wt);

    const int nTiles = (n + 127) / 128;
    gate_kernel<<<dim3(nTiles, 1), 256, T_SMEM>>>(X, idx, b1, W2, b2, n);
    transform_kernel<<<dim3(2, nTiles), 256, T_SMEM>>>(idx, bt, out, n);
}